// round 15
// baseline (speedup 1.0000x reference)
#include <cuda_runtime.h>
#include <cuda_bf16.h>
#include <math.h>
#include <stdint.h>

using bf16 = __nv_bfloat16;

// ---------------------------------------------------------------------------
// Problem constants
// ---------------------------------------------------------------------------
constexpr int Bb = 64, Nn = 128, Dd = 256, Ee = 4, STEPS = 5, ANNOT = 64;
constexpr int Mrows = Bb * Nn;   // 8192
constexpr int EN = Ee * Nn;      // 512

constexpr long long OFF_NODE = 0;
constexpr long long OFF_EDGE = (long long)Mrows * ANNOT;
constexpr long long OFF_MU   = OFF_EDGE + (long long)Mrows * EN;
constexpr long long OFF_VAR  = OFF_MU + (long long)Mrows * Dd;

// ---------------------------------------------------------------------------
// Device scratch (static — allowed)
// ---------------------------------------------------------------------------
__device__ float g_h[Mrows * Dd];
__device__ float g_zb[Mrows * Dd];
__device__ bf16 g_hH[Mrows * Dd],  g_hL[Mrows * Dd];
__device__ bf16 g_ainH[Mrows * Dd], g_ainL[Mrows * Dd];
__device__ bf16 g_rhH[Mrows * Dd],  g_rhL[Mrows * Dd];
__device__ bf16 g_t1H[Mrows * Dd],  g_t1L[Mrows * Dd];
__device__ bf16 g_t2H[Mrows * Dd],  g_t2L[Mrows * Dd];
__device__ bf16 g_zlH[Mrows * Dd],  g_zlL[Mrows * Dd];
__device__ bf16 g_iTH[Bb * Dd * EN], g_iTL[Bb * Dd * EN];   // [b][d][m]
__device__ bf16 g_AinH[Mrows * EN],  g_AinL[Mrows * EN];    // [b*128+n][512]
// Transposed bf16 weights, [n][k]
__device__ bf16 g_WinTH[Ee * Dd * Dd], g_WinTL[Ee * Dd * Dd];
__device__ bf16 g_WrzTH[512 * 512],    g_WrzTL[512 * 512];
__device__ bf16 g_WtTH[256 * 512],     g_WtTL[256 * 512];
__device__ bf16 g_WmvTH[512 * 256],    g_WmvTL[512 * 256];
__device__ bf16 g_Wmu2TH[256 * 256],   g_Wmu2TL[256 * 256];
__device__ bf16 g_Wvr2TH[256 * 256],   g_Wvr2TL[256 * 256];
__device__ bf16 g_WdTH[576 * 256],     g_WdTL[576 * 256];

// ---------------------------------------------------------------------------
// helpers
// ---------------------------------------------------------------------------
__device__ __forceinline__ uint32_t smem_u32(const void* p) {
    uint32_t a;
    asm("{ .reg .u64 t; cvta.to.shared.u64 t, %1; cvt.u32.u64 %0, t; }" : "=r"(a) : "l"(p));
    return a;
}
__device__ __forceinline__ void cpa16(uint32_t dst, const void* src) {
    asm volatile("cp.async.cg.shared.global [%0], [%1], 16;" :: "r"(dst), "l"(src));
}
__device__ __forceinline__ void ldsm4(uint32_t& r0, uint32_t& r1, uint32_t& r2,
                                      uint32_t& r3, uint32_t addr) {
    asm volatile("ldmatrix.sync.aligned.m8n8.x4.shared.b16 {%0,%1,%2,%3}, [%4];"
                 : "=r"(r0), "=r"(r1), "=r"(r2), "=r"(r3) : "r"(addr));
}
__device__ __forceinline__ void mma16816(float& c0, float& c1, float& c2, float& c3,
                                         uint32_t a0, uint32_t a1, uint32_t a2,
                                         uint32_t a3, uint32_t b0, uint32_t b1) {
    asm volatile(
        "mma.sync.aligned.m16n8k16.row.col.f32.bf16.bf16.f32 "
        "{%0,%1,%2,%3},{%4,%5,%6,%7},{%8,%9},{%0,%1,%2,%3};"
        : "+f"(c0), "+f"(c1), "+f"(c2), "+f"(c3)
        : "r"(a0), "r"(a1), "r"(a2), "r"(a3), "r"(b0), "r"(b1));
}
__device__ __forceinline__ void split2(float v, bf16& h, bf16& l) {
    h = __float2bfloat16(v);
    l = __float2bfloat16(v - __bfloat162float(h));
}
__device__ __forceinline__ float sigmoidf_(float x) { return 1.0f / (1.0f + expf(-x)); }

// ---------------------------------------------------------------------------
// mma_gemm: D(128 x 64) = A(128 x K) @ B(64 x K)^T, split-bf16 (3 products),
// fp32 accum. mma.sync.m16n8k16 + ldmatrix + cp.async 2-stage pipeline,
// BK=64 chunks, race-free single __syncthreads per chunk.
// Per-stage smem (48KB): AH(16K) AL(16K) BH(8K) BL(8K). Rows are 128B
// (64 bf16). 16B vector v in [0,8) stored at v ^ (row & 7).
// ---------------------------------------------------------------------------
constexpr int STG = 49152;
constexpr int SMEM_BYTES = 2 * STG;   // 96KB

template <class Spec>
__global__ void __launch_bounds__(256) mma_gemm(Spec s, int K) {
    extern __shared__ __align__(16) unsigned char dynsm[];
    const uint32_t smb = smem_u32(dynsm);

    const int tid = threadIdx.x;
    const int lane = tid & 31, wid = tid >> 5;
    const int wm = wid >> 1, wn = wid & 1;            // warp grid 4 x 2
    const int row0 = blockIdx.y * 128, col0 = blockIdx.x * 64, bz = blockIdx.z;

    const int a_lrow = lane & 15;
    const int a_khi  = (lane >= 16) ? 1 : 0;
    const int b_lrow = (lane & 7) + ((lane >= 16) ? 8 : 0);
    const int b_khi  = (lane & 8) ? 1 : 0;

    float acc[2][4][4] = {};

    auto fill = [&](int c) {
        const int k0 = c * 64;
        const uint32_t base = smb + (c & 1) * STG;
#pragma unroll
        for (int p = 0; p < 12; p++) {
            int j = p * 256 + tid;
            const bf16* src;
            uint32_t arrOff;
            int row, v;
            if (j < 1024)      { row = j >> 3;          v = j & 7; src = s.aH(row0 + row, k0, bz); arrOff = 0; }
            else if (j < 2048) { row = (j - 1024) >> 3; v = j & 7; src = s.aL(row0 + row, k0, bz); arrOff = 16384; }
            else if (j < 2560) { row = (j - 2048) >> 3; v = j & 7; src = s.bH(col0 + row, k0, bz); arrOff = 32768; }
            else               { row = (j - 2560) >> 3; v = j & 7; src = s.bL(col0 + row, k0, bz); arrOff = 40960; }
            int sv = v ^ (row & 7);
            cpa16(base + arrOff + (uint32_t)(row * 128 + sv * 16), src + v * 8);
        }
        asm volatile("cp.async.commit_group;" ::: "memory");
    };

    const int nch = K >> 6;
    fill(0);
    for (int c = 0; c < nch; c++) {
        asm volatile("cp.async.wait_group 0;" ::: "memory");
        __syncthreads();
        if (c + 1 < nch) fill(c + 1);

        const uint32_t aH32 = smb + (c & 1) * STG;
        const uint32_t aL32 = aH32 + 16384, bH32 = aH32 + 32768, bL32 = aH32 + 40960;
#pragma unroll
        for (int ks = 0; ks < 4; ks++) {
            uint32_t ah[2][4], al[2][4], bh[4][2], bl[4][2];
#pragma unroll
            for (int mt = 0; mt < 2; mt++) {
                int r = wm * 32 + mt * 16 + a_lrow;
                int kv = ks * 2 + a_khi;
                uint32_t off = (uint32_t)(r * 128 + ((kv ^ (r & 7)) * 16));
                ldsm4(ah[mt][0], ah[mt][1], ah[mt][2], ah[mt][3], aH32 + off);
                ldsm4(al[mt][0], al[mt][1], al[mt][2], al[mt][3], aL32 + off);
            }
#pragma unroll
            for (int ng = 0; ng < 2; ng++) {
                int r = wn * 32 + ng * 16 + b_lrow;
                int kv = ks * 2 + b_khi;
                uint32_t off = (uint32_t)(r * 128 + ((kv ^ (r & 7)) * 16));
                uint32_t r0, r1, r2, r3;
                ldsm4(r0, r1, r2, r3, bH32 + off);
                bh[ng * 2][0] = r0; bh[ng * 2][1] = r1;
                bh[ng * 2 + 1][0] = r2; bh[ng * 2 + 1][1] = r3;
                ldsm4(r0, r1, r2, r3, bL32 + off);
                bl[ng * 2][0] = r0; bl[ng * 2][1] = r1;
                bl[ng * 2 + 1][0] = r2; bl[ng * 2 + 1][1] = r3;
            }
            // Pass 1: AhBh — 8 independent accumulators
#pragma unroll
            for (int mt = 0; mt < 2; mt++)
#pragma unroll
                for (int nt = 0; nt < 4; nt++) {
                    float* cc = acc[mt][nt];
                    mma16816(cc[0], cc[1], cc[2], cc[3],
                             ah[mt][0], ah[mt][1], ah[mt][2], ah[mt][3],
                             bh[nt][0], bh[nt][1]);
                }
            // Pass 2: AhBl
#pragma unroll
            for (int mt = 0; mt < 2; mt++)
#pragma unroll
                for (int nt = 0; nt < 4; nt++) {
                    float* cc = acc[mt][nt];
                    mma16816(cc[0], cc[1], cc[2], cc[3],
                             ah[mt][0], ah[mt][1], ah[mt][2], ah[mt][3],
                             bl[nt][0], bl[nt][1]);
                }
            // Pass 3: AlBh
#pragma unroll
            for (int mt = 0; mt < 2; mt++)
#pragma unroll
                for (int nt = 0; nt < 4; nt++) {
                    float* cc = acc[mt][nt];
                    mma16816(cc[0], cc[1], cc[2], cc[3],
                             al[mt][0], al[mt][1], al[mt][2], al[mt][3],
                             bh[nt][0], bh[nt][1]);
                }
        }
    }

    const int er = lane >> 2, ec = (lane & 3) * 2;
#pragma unroll
    for (int mt = 0; mt < 2; mt++)
#pragma unroll
        for (int nt = 0; nt < 4; nt++) {
            int r = row0 + wm * 32 + mt * 16 + er;
            int c = col0 + wn * 32 + nt * 8 + ec;
            s.store(r,     c,     acc[mt][nt][0], bz);
            s.store(r,     c + 1, acc[mt][nt][1], bz);
            s.store(r + 8, c,     acc[mt][nt][2], bz);
            s.store(r + 8, c + 1, acc[mt][nt][3], bz);
        }
}

// ---------------------------------------------------------------------------
// Specs (aH/aL/bH/bL must point to 64 valid contiguous bf16 at (row, k0))
// ---------------------------------------------------------------------------
// 1) in_states TRANSPOSED: inst^T = W_in^T @ h^T per batch.
//    M=1024 rows (e*256+f from WinT), N=128 cols (node n'), K=256, bz=batch.
//    Epilogue store is contiguous in col -> coalesced (fixes R14's 2B scatter).
struct TS1 {
    const bf16 *WH, *WL, *hH, *hL; const float* b_in; bf16 *iTH, *iTL;
    __device__ const bf16* aH(int r, int k0, int) const { return WH + r * 256 + k0; }
    __device__ const bf16* aL(int r, int k0, int) const { return WL + r * 256 + k0; }
    __device__ const bf16* bH(int n, int k0, int b) const { return hH + ((long)(b * 128 + n)) * 256 + k0; }
    __device__ const bf16* bL(int n, int k0, int b) const { return hL + ((long)(b * 128 + n)) * 256 + k0; }
    __device__ void store(int row, int col, float v, int b) const {
        int e = row >> 8, f = row & 255;
        float val = v + b_in[row];
        long idx = ((long)(b * 256 + f)) * 512 + e * 128 + col;
        split2(val, iTH[idx], iTL[idx]);
    }
};
struct TS2 {
    const bf16 *AiH, *AiL, *iTH, *iTL; bf16 *aoH, *aoL;
    __device__ const bf16* aH(int r, int k0, int b) const { return AiH + ((long)(b * 128 + r)) * 512 + k0; }
    __device__ const bf16* aL(int r, int k0, int b) const { return AiL + ((long)(b * 128 + r)) * 512 + k0; }
    __device__ const bf16* bH(int n, int k0, int b) const { return iTH + ((long)(b * 256 + n)) * 512 + k0; }
    __device__ const bf16* bL(int n, int k0, int b) const { return iTL + ((long)(b * 256 + n)) * 512 + k0; }
    __device__ void store(int row, int col, float v, int b) const {
        long idx = ((long)(b * 128 + row)) * 256 + col;
        split2(v, aoH[idx], aoL[idx]);
    }
};
struct TS3 {
    const bf16 *anH, *anL, *hH, *hL, *WH, *WL;
    const float *b_r, *b_z, *hf; bf16 *rhH, *rhL; float* zb;
    __device__ const bf16* aH(int r, int k0, int) const {
        return k0 < 256 ? anH + r * 256 + k0 : hH + r * 256 + k0 - 256;
    }
    __device__ const bf16* aL(int r, int k0, int) const {
        return k0 < 256 ? anL + r * 256 + k0 : hL + r * 256 + k0 - 256;
    }
    __device__ const bf16* bH(int n, int k0, int) const { return WH + n * 512 + k0; }
    __device__ const bf16* bL(int n, int k0, int) const { return WL + n * 512 + k0; }
    __device__ void store(int row, int col, float v, int) const {
        if (col < 256) {
            float r = sigmoidf_(v + b_r[col]);
            long idx = (long)row * 256 + col;
            split2(r * hf[idx], rhH[idx], rhL[idx]);
        } else {
            zb[(long)row * 256 + col - 256] = sigmoidf_(v + b_z[col - 256]);
        }
    }
};
struct TS4 {
    const bf16 *anH, *anL, *rhH, *rhL, *WH, *WL;
    const float *b_t, *zb; float* hf; bf16 *hH, *hL;
    __device__ const bf16* aH(int r, int k0, int) const {
        return k0 < 256 ? anH + r * 256 + k0 : rhH + r * 256 + k0 - 256;
    }
    __device__ const bf16* aL(int r, int k0, int) const {
        return k0 < 256 ? anL + r * 256 + k0 : rhL + r * 256 + k0 - 256;
    }
    __device__ const bf16* bH(int n, int k0, int) const { return WH + n * 512 + k0; }
    __device__ const bf16* bL(int n, int k0, int) const { return WL + n * 512 + k0; }
    __device__ void store(int row, int col, float v, int) const {
        float hh = tanhf(v + b_t[col]);
        long idx = (long)row * 256 + col;
        float z = zb[idx];
        float hn = (1.0f - z) * hf[idx] + z * hh;
        hf[idx] = hn;
        split2(hn, hH[idx], hL[idx]);
    }
};
struct TS5 {
    const bf16 *hH, *hL, *WH, *WL; const float *b1, *b2;
    bf16 *t1H, *t1L, *t2H, *t2L;
    __device__ const bf16* aH(int r, int k0, int) const { return hH + r * 256 + k0; }
    __device__ const bf16* aL(int r, int k0, int) const { return hL + r * 256 + k0; }
    __device__ const bf16* bH(int n, int k0, int) const { return WH + n * 256 + k0; }
    __device__ const bf16* bL(int n, int k0, int) const { return WL + n * 256 + k0; }
    __device__ void store(int row, int col, float v, int) const {
        if (col < 256) {
            float t = tanhf(v + b1[col]);
            long idx = (long)row * 256 + col;
            split2(t, t1H[idx], t1L[idx]);
        } else {
            float t = tanhf(v + b2[col - 256]);
            long idx = (long)row * 256 + col - 256;
            split2(t, t2H[idx], t2L[idx]);
        }
    }
};
// batched head linear: bz=0 -> t1@Wmu2 + b_mu2 -> mu; bz=1 -> t2@Wvr2 + b_var2 -> var
struct TS6 {
    const bf16 *X0H, *X0L, *X1H, *X1L, *W0H, *W0L, *W1H, *W1L;
    const float *bias0, *bias1; float *out0, *out1;
    __device__ const bf16* aH(int r, int k0, int b) const {
        return (b ? X1H : X0H) + r * 256 + k0;
    }
    __device__ const bf16* aL(int r, int k0, int b) const {
        return (b ? X1L : X0L) + r * 256 + k0;
    }
    __device__ const bf16* bH(int n, int k0, int b) const {
        return (b ? W1H : W0H) + n * 256 + k0;
    }
    __device__ const bf16* bL(int n, int k0, int b) const {
        return (b ? W1L : W0L) + n * 256 + k0;
    }
    __device__ void store(int row, int col, float v, int b) const {
        if (b) out1[(long)row * 256 + col] = v + bias1[col];
        else   out0[(long)row * 256 + col] = v + bias0[col];
    }
};
struct TS8 {
    const bf16 *XH, *XL, *WH, *WL; const float *b_d1, *b_d2;
    float *node, *edge;
    __device__ const bf16* aH(int r, int k0, int) const { return XH + r * 256 + k0; }
    __device__ const bf16* aL(int r, int k0, int) const { return XL + r * 256 + k0; }
    __device__ const bf16* bH(int n, int k0, int) const { return WH + n * 256 + k0; }
    __device__ const bf16* bL(int n, int k0, int) const { return WL + n * 256 + k0; }
    __device__ void store(int row, int col, float v, int) const {
        if (col < 64) node[(long)row * 64 + col] = v + b_d1[col];
        else          edge[(long)row * 512 + col - 64] = v + b_d2[col - 64];
    }
};

// ---------------------------------------------------------------------------
// Elementwise / preprocessing kernels
// ---------------------------------------------------------------------------
__device__ __forceinline__ unsigned rotl32(unsigned x, int r) { return (x << r) | (x >> (32 - r)); }
__device__ __forceinline__ void threefry2x32_42(unsigned& x0, unsigned& x1) {
    const unsigned ks[3] = {0u, 42u, 0u ^ 42u ^ 0x1BD11BDAu};
    x0 += ks[0]; x1 += ks[1];
    const int R0[4] = {13, 15, 26, 6}, R1[4] = {17, 29, 16, 24};
#pragma unroll
    for (int i = 0; i < 5; i++) {
#pragma unroll
        for (int j = 0; j < 4; j++) {
            int r = (i % 2 == 0) ? R0[j] : R1[j];
            x0 += x1; x1 = rotl32(x1, r); x1 ^= x0;
        }
        x0 += ks[(i + 1) % 3];
        x1 += ks[(i + 2) % 3] + (unsigned)(i + 1);
    }
}
__device__ __forceinline__ float erfinv_xla(float x) {
    float w = -log1pf(-x * x), p;
    if (w < 5.0f) {
        w = w - 2.5f;
        p = 2.81022636e-08f;
        p = fmaf(p, w, 3.43273939e-07f);  p = fmaf(p, w, -3.5233877e-06f);
        p = fmaf(p, w, -4.39150654e-06f); p = fmaf(p, w, 0.00021858087f);
        p = fmaf(p, w, -0.00125372503f);  p = fmaf(p, w, -0.00417768164f);
        p = fmaf(p, w, 0.246640727f);     p = fmaf(p, w, 1.50140941f);
    } else {
        w = sqrtf(w) - 3.0f;
        p = -0.000200214257f;
        p = fmaf(p, w, 0.000100950558f);  p = fmaf(p, w, 0.00134934322f);
        p = fmaf(p, w, -0.00367342844f);  p = fmaf(p, w, 0.00573950773f);
        p = fmaf(p, w, -0.0076224613f);   p = fmaf(p, w, 0.00943887047f);
        p = fmaf(p, w, 1.00167406f);      p = fmaf(p, w, 2.83297682f);
    }
    return p * x;
}
__device__ __forceinline__ float bits_to_normal(unsigned bits) {
    float f = __uint_as_float((bits >> 9) | 0x3f800000u) - 1.0f;
    const float lo = -0.99999994f;
    float u = __fmul_rn(f, 1.0f - lo);
    u = __fadd_rn(u, lo);
    u = fmaxf(lo, u);
    return 1.4142135f * erfinv_xla(u);
}

// Fused transpose-convert for all 13 weight blocks, one launch.
struct ConvJob { const float* src; bf16 *hi, *lo; int K, N; int start; };
struct ConvJobs { ConvJob j[13]; int total; };

__global__ void convAll_k(ConvJobs jobs) {
    int i = blockIdx.x * blockDim.x + threadIdx.x;
    if (i >= jobs.total) return;
#pragma unroll
    for (int t = 0; t < 13; t++) {
        int nxt = (t + 1 < 13) ? jobs.j[t + 1].start : jobs.total;
        if (i >= jobs.j[t].start && i < nxt) {
            const ConvJob& J = jobs.j[t];
            int l = i - J.start;
            int k = l / J.N, n = l % J.N;
            float v = J.src[l];
            bf16 h = __float2bfloat16(v);
            J.hi[(long)n * J.K + k] = h;
            J.lo[(long)n * J.K + k] = __float2bfloat16(v - __bfloat162float(h));
            return;
        }
    }
}

__global__ void convRows_k(const float* __restrict__ src, long stride,
                           bf16* __restrict__ hi, bf16* __restrict__ lo,
                           int R, int K) {
    long i = (long)blockIdx.x * blockDim.x + threadIdx.x;
    if (i >= (long)R * K) return;
    long r = i / K, k = i - r * K;
    float v = src[r * stride + k];
    bf16 h = __float2bfloat16(v);
    hi[i] = h;
    lo[i] = __float2bfloat16(v - __bfloat162float(h));
}

// zlat = eps*exp(0.5*var)+mu, eps inline (threefry partitionable, XOR-fold)
__global__ void zlat_k(const float* __restrict__ mu, const float* __restrict__ var,
                       bf16* __restrict__ zh, bf16* __restrict__ zl) {
    unsigned i = blockIdx.x * blockDim.x + threadIdx.x;
    if (i >= (unsigned)(Mrows * Dd)) return;
    unsigned x0 = 0u, x1 = i;
    threefry2x32_42(x0, x1);
    float eps = bits_to_normal(x0 ^ x1);
    float v = eps * expf(0.5f * var[i]) + mu[i];
    bf16 h = __float2bfloat16(v);
    zh[i] = h;
    zl[i] = __float2bfloat16(v - __bfloat162float(h));
}

// ---------------------------------------------------------------------------
// Launch
// ---------------------------------------------------------------------------
#define GETSYM(var, sym) cudaGetSymbolAddress((void**)&var, sym)

extern "C" void kernel_launch(void* const* d_in, const int* in_sizes, int n_in,
                              void* d_out, int out_size) {
    const float* in[22];
    if (in_sizes[0] == Mrows * Dd) {
        for (int i = 0; i < 22; i++) in[i] = (const float*)d_in[i];
    } else {
        static const int alphaOfDict[22] = {21, 0, 3, 13, 6, 16, 10, 20, 7, 17,
                                            4, 14, 5, 15, 8, 18, 9, 19, 1, 11, 2, 12};
        for (int i = 0; i < 22; i++) in[i] = (const float*)d_in[alphaOfDict[i]];
    }
    const float *prop = in[0], *A = in[1], *W_in = in[2], *b_in = in[3];
    const float *W_r = in[4], *b_r = in[5], *W_z = in[6], *b_z = in[7];
    const float *W_t = in[8], *b_t = in[9];
    const float *W_mu1 = in[10], *b_mu1 = in[11], *W_mu2 = in[12], *b_mu2 = in[13];
    const float *W_var1 = in[14], *b_var1 = in[15], *W_var2 = in[16], *b_var2 = in[17];
    const float *W_d1 = in[18], *b_d1 = in[19], *W_d2 = in[20], *b_d2 = in[21];
    float* out = (float*)d_out;

    float *hf, *zb;
    bf16 *hH, *hL, *anH, *anL, *rhH, *rhL, *t1H, *t1L, *t2H, *t2L, *zlH, *zlL;
    bf16 *iTH, *iTL, *AiH, *AiL;
    bf16 *WinTH, *WinTL, *WrzTH, *WrzTL, *WtTH, *WtTL, *WmvTH, *WmvTL;
    bf16 *Wmu2TH, *Wmu2TL, *Wvr2TH, *Wvr2TL, *WdTH, *WdTL;
    GETSYM(hf, g_h); GETSYM(zb, g_zb);
    GETSYM(hH, g_hH); GETSYM(hL, g_hL); GETSYM(anH, g_ainH); GETSYM(anL, g_ainL);
    GETSYM(rhH, g_rhH); GETSYM(rhL, g_rhL);
    GETSYM(t1H, g_t1H); GETSYM(t1L, g_t1L); GETSYM(t2H, g_t2H); GETSYM(t2L, g_t2L);
    GETSYM(zlH, g_zlH); GETSYM(zlL, g_zlL);
    GETSYM(iTH, g_iTH); GETSYM(iTL, g_iTL); GETSYM(AiH, g_AinH); GETSYM(AiL, g_AinL);
    GETSYM(WinTH, g_WinTH); GETSYM(WinTL, g_WinTL);
    GETSYM(WrzTH, g_WrzTH); GETSYM(WrzTL, g_WrzTL);
    GETSYM(WtTH, g_WtTH); GETSYM(WtTL, g_WtTL);
    GETSYM(WmvTH, g_WmvTH); GETSYM(WmvTL, g_WmvTL);
    GETSYM(Wmu2TH, g_Wmu2TH); GETSYM(Wmu2TL, g_Wmu2TL);
    GETSYM(Wvr2TH, g_Wvr2TH); GETSYM(Wvr2TL, g_Wvr2TL);
    GETSYM(WdTH, g_WdTH); GETSYM(WdTL, g_WdTL);

    cudaFuncSetAttribute(mma_gemm<TS1>, cudaFuncAttributeMaxDynamicSharedMemorySize, SMEM_BYTES);
    cudaFuncSetAttribute(mma_gemm<TS2>, cudaFuncAttributeMaxDynamicSharedMemorySize, SMEM_BYTES);
    cudaFuncSetAttribute(mma_gemm<TS3>, cudaFuncAttributeMaxDynamicSharedMemorySize, SMEM_BYTES);
    cudaFuncSetAttribute(mma_gemm<TS4>, cudaFuncAttributeMaxDynamicSharedMemorySize, SMEM_BYTES);
    cudaFuncSetAttribute(mma_gemm<TS5>, cudaFuncAttributeMaxDynamicSharedMemorySize, SMEM_BYTES);
    cudaFuncSetAttribute(mma_gemm<TS6>, cudaFuncAttributeMaxDynamicSharedMemorySize, SMEM_BYTES);
    cudaFuncSetAttribute(mma_gemm<TS8>, cudaFuncAttributeMaxDynamicSharedMemorySize, SMEM_BYTES);

    // h0 (fp32 + split), A_in split
    cudaMemcpyAsync(hf, prop, (size_t)Mrows * Dd * sizeof(float), cudaMemcpyDeviceToDevice);
    convRows_k<<<((long)Mrows * Dd + 255) / 256, 256>>>(prop, 256, hH, hL, Mrows, 256);
    convRows_k<<<((long)Mrows * EN + 255) / 256, 256>>>(A, 1024, AiH, AiL, Mrows, 512);

    // all 13 weight blocks -> transposed bf16 hi/lo, one fused launch
    {
        ConvJobs cj;
        int off = 0;
        auto add = [&](int idx, const float* src, bf16* hi, bf16* lo, int K, int N) {
            cj.j[idx] = {src, hi, lo, K, N, off};
            off += K * N;
        };
        add(0, W_in, WinTH, WinTL, 256, 256);
        add(1, W_in + 65536, WinTH + 65536, WinTL + 65536, 256, 256);
        add(2, W_in + 131072, WinTH + 131072, WinTL + 131072, 256, 256);
        add(3, W_in + 196608, WinTH + 196608, WinTL + 196608, 256, 256);
        add(4, W_r, WrzTH, WrzTL, 512, 256);
        add(5, W_z, WrzTH + 256 * 512, WrzTL + 256 * 512, 512, 256);
        add(6, W_t, WtTH, WtTL, 512, 256);
        add(7, W_mu1, WmvTH, WmvTL, 256, 256);
        add(8, W_var1, WmvTH + 256 * 256, WmvTL + 256 * 256, 256, 256);
        add(9, W_mu2, Wmu2TH, Wmu2TL, 256, 256);
        add(10, W_var2, Wvr2TH, Wvr2TL, 256, 256);
        add(11, W_d1, WdTH, WdTL, 256, 64);
        add(12, W_d2, WdTH + 64 * 256, WdTL + 64 * 256, 256, 512);
        cj.total = off;
        convAll_k<<<(cj.total + 255) / 256, 256>>>(cj);
    }

    for (int step = 0; step < STEPS; step++) {
        // inst^T = W_in^T @ h^T (per batch): M=1024, N=128, K=256
        mma_gemm<TS1><<<dim3(2, 8, 64), 256, SMEM_BYTES>>>(
            TS1{WinTH, WinTL, hH, hL, b_in, iTH, iTL}, 256);
        mma_gemm<TS2><<<dim3(4, 1, 64), 256, SMEM_BYTES>>>(
            TS2{AiH, AiL, iTH, iTL, anH, anL}, 512);
        mma_gemm<TS3><<<dim3(8, 64, 1), 256, SMEM_BYTES>>>(
            TS3{anH, anL, hH, hL, WrzTH, WrzTL, b_r, b_z, hf, rhH, rhL, zb}, 512);
        mma_gemm<TS4><<<dim3(4, 64, 1), 256, SMEM_BYTES>>>(
            TS4{anH, anL, rhH, rhL, WtTH, WtTL, b_t, zb, hf, hH, hL}, 512);
    }

    mma_gemm<TS5><<<dim3(8, 64, 1), 256, SMEM_BYTES>>>(
        TS5{hH, hL, WmvTH, WmvTL, b_mu1, b_var1, t1H, t1L, t2H, t2L}, 256);
    mma_gemm<TS6><<<dim3(4, 64, 2), 256, SMEM_BYTES>>>(
        TS6{t1H, t1L, t2H, t2L, Wmu2TH, Wmu2TL, Wvr2TH, Wvr2TL,
            b_mu2, b_var2, out + OFF_MU, out + OFF_VAR}, 256);
    zlat_k<<<(Mrows * Dd + 255) / 256, 256>>>(out + OFF_MU, out + OFF_VAR, zlH, zlL);
    mma_gemm<TS8><<<dim3(9, 64, 1), 256, SMEM_BYTES>>>(
        TS8{zlH, zlL, WdTH, WdTL, b_d1, b_d2, out + OFF_NODE, out + OFF_EDGE}, 256);
}

// round 16
// speedup vs baseline: 1.2411x; 1.2411x over previous
#include <cuda_runtime.h>
#include <cuda_bf16.h>
#include <math.h>
#include <stdint.h>

using bf16 = __nv_bfloat16;

// ---------------------------------------------------------------------------
// Problem constants
// ---------------------------------------------------------------------------
constexpr int Bb = 64, Nn = 128, Dd = 256, Ee = 4, STEPS = 5, ANNOT = 64;
constexpr int Mrows = Bb * Nn;   // 8192
constexpr int EN = Ee * Nn;      // 512

constexpr long long OFF_NODE = 0;
constexpr long long OFF_EDGE = (long long)Mrows * ANNOT;
constexpr long long OFF_MU   = OFF_EDGE + (long long)Mrows * EN;
constexpr long long OFF_VAR  = OFF_MU + (long long)Mrows * Dd;

// ---------------------------------------------------------------------------
// Device scratch (static — allowed)
// ---------------------------------------------------------------------------
__device__ float g_h[Mrows * Dd];
__device__ float g_zb[Mrows * Dd];
__device__ bf16 g_hH[Mrows * Dd],  g_hL[Mrows * Dd];
__device__ bf16 g_ainH[Mrows * Dd], g_ainL[Mrows * Dd];
__device__ bf16 g_rhH[Mrows * Dd],  g_rhL[Mrows * Dd];
__device__ bf16 g_t1H[Mrows * Dd],  g_t1L[Mrows * Dd];
__device__ bf16 g_t2H[Mrows * Dd],  g_t2L[Mrows * Dd];
__device__ bf16 g_zlH[Mrows * Dd],  g_zlL[Mrows * Dd];
__device__ bf16 g_iTH[Bb * Dd * EN], g_iTL[Bb * Dd * EN];   // [b][d][m]
__device__ bf16 g_AinH[Mrows * EN],  g_AinL[Mrows * EN];    // [b*128+n][512]
// Transposed bf16 weights, [n][k]
__device__ bf16 g_WinTH[Ee * Dd * Dd], g_WinTL[Ee * Dd * Dd];
__device__ bf16 g_WrzTH[512 * 512],    g_WrzTL[512 * 512];
__device__ bf16 g_WtTH[256 * 512],     g_WtTL[256 * 512];
__device__ bf16 g_WmvTH[512 * 256],    g_WmvTL[512 * 256];
__device__ bf16 g_Wmu2TH[256 * 256],   g_Wmu2TL[256 * 256];
__device__ bf16 g_Wvr2TH[256 * 256],   g_Wvr2TL[256 * 256];
__device__ bf16 g_WdTH[576 * 256],     g_WdTL[576 * 256];

// ---------------------------------------------------------------------------
// helpers
// ---------------------------------------------------------------------------
__device__ __forceinline__ uint32_t smem_u32(const void* p) {
    uint32_t a;
    asm("{ .reg .u64 t; cvta.to.shared.u64 t, %1; cvt.u32.u64 %0, t; }" : "=r"(a) : "l"(p));
    return a;
}
__device__ __forceinline__ void cpa16(uint32_t dst, const void* src) {
    asm volatile("cp.async.cg.shared.global [%0], [%1], 16;" :: "r"(dst), "l"(src));
}
__device__ __forceinline__ void ldsm4(uint32_t& r0, uint32_t& r1, uint32_t& r2,
                                      uint32_t& r3, uint32_t addr) {
    asm volatile("ldmatrix.sync.aligned.m8n8.x4.shared.b16 {%0,%1,%2,%3}, [%4];"
                 : "=r"(r0), "=r"(r1), "=r"(r2), "=r"(r3) : "r"(addr));
}
__device__ __forceinline__ void mma16816(float& c0, float& c1, float& c2, float& c3,
                                         uint32_t a0, uint32_t a1, uint32_t a2,
                                         uint32_t a3, uint32_t b0, uint32_t b1) {
    asm volatile(
        "mma.sync.aligned.m16n8k16.row.col.f32.bf16.bf16.f32 "
        "{%0,%1,%2,%3},{%4,%5,%6,%7},{%8,%9},{%0,%1,%2,%3};"
        : "+f"(c0), "+f"(c1), "+f"(c2), "+f"(c3)
        : "r"(a0), "r"(a1), "r"(a2), "r"(a3), "r"(b0), "r"(b1));
}
__device__ __forceinline__ void split2(float v, bf16& h, bf16& l) {
    h = __float2bfloat16(v);
    l = __float2bfloat16(v - __bfloat162float(h));
}
// packed split-store of two col-adjacent values (idx must be even)
__device__ __forceinline__ void split2pack(float v0, float v1,
                                           bf16* __restrict__ hi,
                                           bf16* __restrict__ lo, long idx) {
    bf16 h0, l0, h1, l1;
    split2(v0, h0, l0);
    split2(v1, h1, l1);
    __nv_bfloat162 hh; hh.x = h0; hh.y = h1;
    __nv_bfloat162 ll; ll.x = l0; ll.y = l1;
    *(__nv_bfloat162*)(hi + idx) = hh;
    *(__nv_bfloat162*)(lo + idx) = ll;
}
__device__ __forceinline__ float sigmoidf_(float x) { return 1.0f / (1.0f + expf(-x)); }

// ---------------------------------------------------------------------------
// mma_gemm: D(128 x 64) = A(128 x K) @ B(64 x K)^T, split-bf16 (3 products),
// fp32 accum. mma.sync.m16n8k16 + ldmatrix + cp.async 2-stage pipeline,
// BK=64 chunks, race-free single __syncthreads per chunk.
// Epilogue uses paired stores: Spec::store2(row, col, v0, v1, bz) writes
// (row,col) and (row,col+1) — one vector store for col-contiguous outputs.
// Per-stage smem (48KB): AH(16K) AL(16K) BH(8K) BL(8K). Rows are 128B
// (64 bf16). 16B vector v in [0,8) stored at v ^ (row & 7).
// ---------------------------------------------------------------------------
constexpr int STG = 49152;
constexpr int SMEM_BYTES = 2 * STG;   // 96KB

template <class Spec>
__global__ void __launch_bounds__(256) mma_gemm(Spec s, int K) {
    extern __shared__ __align__(16) unsigned char dynsm[];
    const uint32_t smb = smem_u32(dynsm);

    const int tid = threadIdx.x;
    const int lane = tid & 31, wid = tid >> 5;
    const int wm = wid >> 1, wn = wid & 1;            // warp grid 4 x 2
    const int row0 = blockIdx.y * 128, col0 = blockIdx.x * 64, bz = blockIdx.z;

    const int a_lrow = lane & 15;
    const int a_khi  = (lane >= 16) ? 1 : 0;
    const int b_lrow = (lane & 7) + ((lane >= 16) ? 8 : 0);
    const int b_khi  = (lane & 8) ? 1 : 0;

    float acc[2][4][4] = {};

    auto fill = [&](int c) {
        const int k0 = c * 64;
        const uint32_t base = smb + (c & 1) * STG;
#pragma unroll
        for (int p = 0; p < 12; p++) {
            int j = p * 256 + tid;
            const bf16* src;
            uint32_t arrOff;
            int row, v;
            if (j < 1024)      { row = j >> 3;          v = j & 7; src = s.aH(row0 + row, k0, bz); arrOff = 0; }
            else if (j < 2048) { row = (j - 1024) >> 3; v = j & 7; src = s.aL(row0 + row, k0, bz); arrOff = 16384; }
            else if (j < 2560) { row = (j - 2048) >> 3; v = j & 7; src = s.bH(col0 + row, k0, bz); arrOff = 32768; }
            else               { row = (j - 2560) >> 3; v = j & 7; src = s.bL(col0 + row, k0, bz); arrOff = 40960; }
            int sv = v ^ (row & 7);
            cpa16(base + arrOff + (uint32_t)(row * 128 + sv * 16), src + v * 8);
        }
        asm volatile("cp.async.commit_group;" ::: "memory");
    };

    const int nch = K >> 6;
    fill(0);
    for (int c = 0; c < nch; c++) {
        asm volatile("cp.async.wait_group 0;" ::: "memory");
        __syncthreads();
        if (c + 1 < nch) fill(c + 1);

        const uint32_t aH32 = smb + (c & 1) * STG;
        const uint32_t aL32 = aH32 + 16384, bH32 = aH32 + 32768, bL32 = aH32 + 40960;
#pragma unroll
        for (int ks = 0; ks < 4; ks++) {
            uint32_t ah[2][4], al[2][4], bh[4][2], bl[4][2];
#pragma unroll
            for (int mt = 0; mt < 2; mt++) {
                int r = wm * 32 + mt * 16 + a_lrow;
                int kv = ks * 2 + a_khi;
                uint32_t off = (uint32_t)(r * 128 + ((kv ^ (r & 7)) * 16));
                ldsm4(ah[mt][0], ah[mt][1], ah[mt][2], ah[mt][3], aH32 + off);
                ldsm4(al[mt][0], al[mt][1], al[mt][2], al[mt][3], aL32 + off);
            }
#pragma unroll
            for (int ng = 0; ng < 2; ng++) {
                int r = wn * 32 + ng * 16 + b_lrow;
                int kv = ks * 2 + b_khi;
                uint32_t off = (uint32_t)(r * 128 + ((kv ^ (r & 7)) * 16));
                uint32_t r0, r1, r2, r3;
                ldsm4(r0, r1, r2, r3, bH32 + off);
                bh[ng * 2][0] = r0; bh[ng * 2][1] = r1;
                bh[ng * 2 + 1][0] = r2; bh[ng * 2 + 1][1] = r3;
                ldsm4(r0, r1, r2, r3, bL32 + off);
                bl[ng * 2][0] = r0; bl[ng * 2][1] = r1;
                bl[ng * 2 + 1][0] = r2; bl[ng * 2 + 1][1] = r3;
            }
            // Pass 1: AhBh — 8 independent accumulators
#pragma unroll
            for (int mt = 0; mt < 2; mt++)
#pragma unroll
                for (int nt = 0; nt < 4; nt++) {
                    float* cc = acc[mt][nt];
                    mma16816(cc[0], cc[1], cc[2], cc[3],
                             ah[mt][0], ah[mt][1], ah[mt][2], ah[mt][3],
                             bh[nt][0], bh[nt][1]);
                }
            // Pass 2: AhBl
#pragma unroll
            for (int mt = 0; mt < 2; mt++)
#pragma unroll
                for (int nt = 0; nt < 4; nt++) {
                    float* cc = acc[mt][nt];
                    mma16816(cc[0], cc[1], cc[2], cc[3],
                             ah[mt][0], ah[mt][1], ah[mt][2], ah[mt][3],
                             bl[nt][0], bl[nt][1]);
                }
            // Pass 3: AlBh
#pragma unroll
            for (int mt = 0; mt < 2; mt++)
#pragma unroll
                for (int nt = 0; nt < 4; nt++) {
                    float* cc = acc[mt][nt];
                    mma16816(cc[0], cc[1], cc[2], cc[3],
                             al[mt][0], al[mt][1], al[mt][2], al[mt][3],
                             bh[nt][0], bh[nt][1]);
                }
        }
    }

    const int er = lane >> 2, ec = (lane & 3) * 2;
#pragma unroll
    for (int mt = 0; mt < 2; mt++)
#pragma unroll
        for (int nt = 0; nt < 4; nt++) {
            int r = row0 + wm * 32 + mt * 16 + er;
            int c = col0 + wn * 32 + nt * 8 + ec;
            s.store2(r,     c, acc[mt][nt][0], acc[mt][nt][1], bz);
            s.store2(r + 8, c, acc[mt][nt][2], acc[mt][nt][3], bz);
        }
}

// ---------------------------------------------------------------------------
// Specs (aH/aL/bH/bL must point to 64 valid contiguous bf16 at (row, k0);
// store2 writes (row,col) and (row,col+1), col even)
// ---------------------------------------------------------------------------
// 1) in_states: A=h (8192x256), B=WinT (1024x256); write instT hi/lo [b][d][m]
//    Output contiguous in ROW (nn), so cols aren't adjacent -> scalar stores.
struct TS1 {
    const bf16 *hH, *hL, *WH, *WL; const float* b_in; bf16 *iTH, *iTL;
    __device__ const bf16* aH(int r, int k0, int) const { return hH + r * 256 + k0; }
    __device__ const bf16* aL(int r, int k0, int) const { return hL + r * 256 + k0; }
    __device__ const bf16* bH(int n, int k0, int) const { return WH + n * 256 + k0; }
    __device__ const bf16* bL(int n, int k0, int) const { return WL + n * 256 + k0; }
    __device__ void store2(int row, int col, float v0, float v1, int) const {
        int b = row >> 7, nn = row & 127;
#pragma unroll
        for (int q = 0; q < 2; q++) {
            int cc = col + q;
            int e = cc >> 8, f = cc & 255;
            float val = (q ? v1 : v0) + b_in[e * 256 + f];
            long idx = ((long)(b * 256 + f)) * 512 + e * 128 + nn;
            split2(val, iTH[idx], iTL[idx]);
        }
    }
};
struct TS2 {
    const bf16 *AiH, *AiL, *iTH, *iTL; bf16 *aoH, *aoL;
    __device__ const bf16* aH(int r, int k0, int b) const { return AiH + ((long)(b * 128 + r)) * 512 + k0; }
    __device__ const bf16* aL(int r, int k0, int b) const { return AiL + ((long)(b * 128 + r)) * 512 + k0; }
    __device__ const bf16* bH(int n, int k0, int b) const { return iTH + ((long)(b * 256 + n)) * 512 + k0; }
    __device__ const bf16* bL(int n, int k0, int b) const { return iTL + ((long)(b * 256 + n)) * 512 + k0; }
    __device__ void store2(int row, int col, float v0, float v1, int b) const {
        long idx = ((long)(b * 128 + row)) * 256 + col;
        split2pack(v0, v1, aoH, aoL, idx);
    }
};
struct TS3 {
    const bf16 *anH, *anL, *hH, *hL, *WH, *WL;
    const float *b_r, *b_z, *hf; bf16 *rhH, *rhL; float* zb;
    __device__ const bf16* aH(int r, int k0, int) const {
        return k0 < 256 ? anH + r * 256 + k0 : hH + r * 256 + k0 - 256;
    }
    __device__ const bf16* aL(int r, int k0, int) const {
        return k0 < 256 ? anL + r * 256 + k0 : hL + r * 256 + k0 - 256;
    }
    __device__ const bf16* bH(int n, int k0, int) const { return WH + n * 512 + k0; }
    __device__ const bf16* bL(int n, int k0, int) const { return WL + n * 512 + k0; }
    __device__ void store2(int row, int col, float v0, float v1, int) const {
        if (col < 256) {
            long idx = (long)row * 256 + col;
            float r0 = sigmoidf_(v0 + b_r[col]) * hf[idx];
            float r1 = sigmoidf_(v1 + b_r[col + 1]) * hf[idx + 1];
            split2pack(r0, r1, rhH, rhL, idx);
        } else {
            long idx = (long)row * 256 + col - 256;
            float2 z;
            z.x = sigmoidf_(v0 + b_z[col - 256]);
            z.y = sigmoidf_(v1 + b_z[col - 255]);
            *(float2*)(zb + idx) = z;
        }
    }
};
struct TS4 {
    const bf16 *anH, *anL, *rhH, *rhL, *WH, *WL;
    const float *b_t, *zb; float* hf; bf16 *hH, *hL;
    __device__ const bf16* aH(int r, int k0, int) const {
        return k0 < 256 ? anH + r * 256 + k0 : rhH + r * 256 + k0 - 256;
    }
    __device__ const bf16* aL(int r, int k0, int) const {
        return k0 < 256 ? anL + r * 256 + k0 : rhL + r * 256 + k0 - 256;
    }
    __device__ const bf16* bH(int n, int k0, int) const { return WH + n * 512 + k0; }
    __device__ const bf16* bL(int n, int k0, int) const { return WL + n * 512 + k0; }
    __device__ void store2(int row, int col, float v0, float v1, int) const {
        long idx = (long)row * 256 + col;
        float hh0 = tanhf(v0 + b_t[col]);
        float hh1 = tanhf(v1 + b_t[col + 1]);
        float z0 = zb[idx], z1 = zb[idx + 1];
        float hn0 = (1.0f - z0) * hf[idx] + z0 * hh0;
        float hn1 = (1.0f - z1) * hf[idx + 1] + z1 * hh1;
        float2 hv; hv.x = hn0; hv.y = hn1;
        *(float2*)(hf + idx) = hv;
        split2pack(hn0, hn1, hH, hL, idx);
    }
};
struct TS5 {
    const bf16 *hH, *hL, *WH, *WL; const float *b1, *b2;
    bf16 *t1H, *t1L, *t2H, *t2L;
    __device__ const bf16* aH(int r, int k0, int) const { return hH + r * 256 + k0; }
    __device__ const bf16* aL(int r, int k0, int) const { return hL + r * 256 + k0; }
    __device__ const bf16* bH(int n, int k0, int) const { return WH + n * 256 + k0; }
    __device__ const bf16* bL(int n, int k0, int) const { return WL + n * 256 + k0; }
    __device__ void store2(int row, int col, float v0, float v1, int) const {
        if (col < 256) {
            long idx = (long)row * 256 + col;
            split2pack(tanhf(v0 + b1[col]), tanhf(v1 + b1[col + 1]), t1H, t1L, idx);
        } else {
            long idx = (long)row * 256 + col - 256;
            split2pack(tanhf(v0 + b2[col - 256]), tanhf(v1 + b2[col - 255]),
                       t2H, t2L, idx);
        }
    }
};
// batched head linear: bz=0 -> t1@Wmu2 + b_mu2 -> mu; bz=1 -> t2@Wvr2 + b_var2 -> var
struct TS6 {
    const bf16 *X0H, *X0L, *X1H, *X1L, *W0H, *W0L, *W1H, *W1L;
    const float *bias0, *bias1; float *out0, *out1;
    __device__ const bf16* aH(int r, int k0, int b) const {
        return (b ? X1H : X0H) + r * 256 + k0;
    }
    __device__ const bf16* aL(int r, int k0, int b) const {
        return (b ? X1L : X0L) + r * 256 + k0;
    }
    __device__ const bf16* bH(int n, int k0, int b) const {
        return (b ? W1H : W0H) + n * 256 + k0;
    }
    __device__ const bf16* bL(int n, int k0, int b) const {
        return (b ? W1L : W0L) + n * 256 + k0;
    }
    __device__ void store2(int row, int col, float v0, float v1, int b) const {
        const float* bias = b ? bias1 : bias0;
        float* out = b ? out1 : out0;
        float2 v; v.x = v0 + bias[col]; v.y = v1 + bias[col + 1];
        *(float2*)(out + (long)row * 256 + col) = v;
    }
};
struct TS8 {
    const bf16 *XH, *XL, *WH, *WL; const float *b_d1, *b_d2;
    float *node, *edge;
    __device__ const bf16* aH(int r, int k0, int) const { return XH + r * 256 + k0; }
    __device__ const bf16* aL(int r, int k0, int) const { return XL + r * 256 + k0; }
    __device__ const bf16* bH(int n, int k0, int) const { return WH + n * 256 + k0; }
    __device__ const bf16* bL(int n, int k0, int) const { return WL + n * 256 + k0; }
    __device__ void store2(int row, int col, float v0, float v1, int) const {
        if (col < 64) {
            float2 v; v.x = v0 + b_d1[col]; v.y = v1 + b_d1[col + 1];
            *(float2*)(node + (long)row * 64 + col) = v;
        } else {
            float2 v; v.x = v0 + b_d2[col - 64]; v.y = v1 + b_d2[col - 63];
            *(float2*)(edge + (long)row * 512 + col - 64) = v;
        }
    }
};

// ---------------------------------------------------------------------------
// Elementwise / preprocessing kernels
// ---------------------------------------------------------------------------
__device__ __forceinline__ unsigned rotl32(unsigned x, int r) { return (x << r) | (x >> (32 - r)); }
__device__ __forceinline__ void threefry2x32_42(unsigned& x0, unsigned& x1) {
    const unsigned ks[3] = {0u, 42u, 0u ^ 42u ^ 0x1BD11BDAu};
    x0 += ks[0]; x1 += ks[1];
    const int R0[4] = {13, 15, 26, 6}, R1[4] = {17, 29, 16, 24};
#pragma unroll
    for (int i = 0; i < 5; i++) {
#pragma unroll
        for (int j = 0; j < 4; j++) {
            int r = (i % 2 == 0) ? R0[j] : R1[j];
            x0 += x1; x1 = rotl32(x1, r); x1 ^= x0;
        }
        x0 += ks[(i + 1) % 3];
        x1 += ks[(i + 2) % 3] + (unsigned)(i + 1);
    }
}
__device__ __forceinline__ float erfinv_xla(float x) {
    float w = -log1pf(-x * x), p;
    if (w < 5.0f) {
        w = w - 2.5f;
        p = 2.81022636e-08f;
        p = fmaf(p, w, 3.43273939e-07f);  p = fmaf(p, w, -3.5233877e-06f);
        p = fmaf(p, w, -4.39150654e-06f); p = fmaf(p, w, 0.00021858087f);
        p = fmaf(p, w, -0.00125372503f);  p = fmaf(p, w, -0.00417768164f);
        p = fmaf(p, w, 0.246640727f);     p = fmaf(p, w, 1.50140941f);
    } else {
        w = sqrtf(w) - 3.0f;
        p = -0.000200214257f;
        p = fmaf(p, w, 0.000100950558f);  p = fmaf(p, w, 0.00134934322f);
        p = fmaf(p, w, -0.00367342844f);  p = fmaf(p, w, 0.00573950773f);
        p = fmaf(p, w, -0.0076224613f);   p = fmaf(p, w, 0.00943887047f);
        p = fmaf(p, w, 1.00167406f);      p = fmaf(p, w, 2.83297682f);
    }
    return p * x;
}
__device__ __forceinline__ float bits_to_normal(unsigned bits) {
    float f = __uint_as_float((bits >> 9) | 0x3f800000u) - 1.0f;
    const float lo = -0.99999994f;
    float u = __fmul_rn(f, 1.0f - lo);
    u = __fadd_rn(u, lo);
    u = fmaxf(lo, u);
    return 1.4142135f * erfinv_xla(u);
}

// Fused transpose-convert for all 13 weight blocks, one launch.
struct ConvJob { const float* src; bf16 *hi, *lo; int K, N; int start; };
struct ConvJobs { ConvJob j[13]; int total; };

__global__ void convAll_k(ConvJobs jobs) {
    int i = blockIdx.x * blockDim.x + threadIdx.x;
    if (i >= jobs.total) return;
#pragma unroll
    for (int t = 0; t < 13; t++) {
        int nxt = (t + 1 < 13) ? jobs.j[t + 1].start : jobs.total;
        if (i >= jobs.j[t].start && i < nxt) {
            const ConvJob& J = jobs.j[t];
            int l = i - J.start;
            int k = l / J.N, n = l % J.N;
            float v = J.src[l];
            bf16 h = __float2bfloat16(v);
            J.hi[(long)n * J.K + k] = h;
            J.lo[(long)n * J.K + k] = __float2bfloat16(v - __bfloat162float(h));
            return;
        }
    }
}

__global__ void convRows_k(const float* __restrict__ src, long stride,
                           bf16* __restrict__ hi, bf16* __restrict__ lo,
                           int R, int K) {
    long i = (long)blockIdx.x * blockDim.x + threadIdx.x;
    if (i >= (long)R * K) return;
    long r = i / K, k = i - r * K;
    float v = src[r * stride + k];
    bf16 h = __float2bfloat16(v);
    hi[i] = h;
    lo[i] = __float2bfloat16(v - __bfloat162float(h));
}

// zlat = eps*exp(0.5*var)+mu, eps inline (threefry partitionable, XOR-fold)
__global__ void zlat_k(const float* __restrict__ mu, const float* __restrict__ var,
                       bf16* __restrict__ zh, bf16* __restrict__ zl) {
    unsigned i = blockIdx.x * blockDim.x + threadIdx.x;
    if (i >= (unsigned)(Mrows * Dd)) return;
    unsigned x0 = 0u, x1 = i;
    threefry2x32_42(x0, x1);
    float eps = bits_to_normal(x0 ^ x1);
    float v = eps * expf(0.5f * var[i]) + mu[i];
    bf16 h = __float2bfloat16(v);
    zh[i] = h;
    zl[i] = __float2bfloat16(v - __bfloat162float(h));
}

// ---------------------------------------------------------------------------
// Launch
// ---------------------------------------------------------------------------
#define GETSYM(var, sym) cudaGetSymbolAddress((void**)&var, sym)

extern "C" void kernel_launch(void* const* d_in, const int* in_sizes, int n_in,
                              void* d_out, int out_size) {
    const float* in[22];
    if (in_sizes[0] == Mrows * Dd) {
        for (int i = 0; i < 22; i++) in[i] = (const float*)d_in[i];
    } else {
        static const int alphaOfDict[22] = {21, 0, 3, 13, 6, 16, 10, 20, 7, 17,
                                            4, 14, 5, 15, 8, 18, 9, 19, 1, 11, 2, 12};
        for (int i = 0; i < 22; i++) in[i] = (const float*)d_in[alphaOfDict[i]];
    }
    const float *prop = in[0], *A = in[1], *W_in = in[2], *b_in = in[3];
    const float *W_r = in[4], *b_r = in[5], *W_z = in[6], *b_z = in[7];
    const float *W_t = in[8], *b_t = in[9];
    const float *W_mu1 = in[10], *b_mu1 = in[11], *W_mu2 = in[12], *b_mu2 = in[13];
    const float *W_var1 = in[14], *b_var1 = in[15], *W_var2 = in[16], *b_var2 = in[17];
    const float *W_d1 = in[18], *b_d1 = in[19], *W_d2 = in[20], *b_d2 = in[21];
    float* out = (float*)d_out;

    float *hf, *zb;
    bf16 *hH, *hL, *anH, *anL, *rhH, *rhL, *t1H, *t1L, *t2H, *t2L, *zlH, *zlL;
    bf16 *iTH, *iTL, *AiH, *AiL;
    bf16 *WinTH, *WinTL, *WrzTH, *WrzTL, *WtTH, *WtTL, *WmvTH, *WmvTL;
    bf16 *Wmu2TH, *Wmu2TL, *Wvr2TH, *Wvr2TL, *WdTH, *WdTL;
    GETSYM(hf, g_h); GETSYM(zb, g_zb);
    GETSYM(hH, g_hH); GETSYM(hL, g_hL); GETSYM(anH, g_ainH); GETSYM(anL, g_ainL);
    GETSYM(rhH, g_rhH); GETSYM(rhL, g_rhL);
    GETSYM(t1H, g_t1H); GETSYM(t1L, g_t1L); GETSYM(t2H, g_t2H); GETSYM(t2L, g_t2L);
    GETSYM(zlH, g_zlH); GETSYM(zlL, g_zlL);
    GETSYM(iTH, g_iTH); GETSYM(iTL, g_iTL); GETSYM(AiH, g_AinH); GETSYM(AiL, g_AinL);
    GETSYM(WinTH, g_WinTH); GETSYM(WinTL, g_WinTL);
    GETSYM(WrzTH, g_WrzTH); GETSYM(WrzTL, g_WrzTL);
    GETSYM(WtTH, g_WtTH); GETSYM(WtTL, g_WtTL);
    GETSYM(WmvTH, g_WmvTH); GETSYM(WmvTL, g_WmvTL);
    GETSYM(Wmu2TH, g_Wmu2TH); GETSYM(Wmu2TL, g_Wmu2TL);
    GETSYM(Wvr2TH, g_Wvr2TH); GETSYM(Wvr2TL, g_Wvr2TL);
    GETSYM(WdTH, g_WdTH); GETSYM(WdTL, g_WdTL);

    cudaFuncSetAttribute(mma_gemm<TS1>, cudaFuncAttributeMaxDynamicSharedMemorySize, SMEM_BYTES);
    cudaFuncSetAttribute(mma_gemm<TS2>, cudaFuncAttributeMaxDynamicSharedMemorySize, SMEM_BYTES);
    cudaFuncSetAttribute(mma_gemm<TS3>, cudaFuncAttributeMaxDynamicSharedMemorySize, SMEM_BYTES);
    cudaFuncSetAttribute(mma_gemm<TS4>, cudaFuncAttributeMaxDynamicSharedMemorySize, SMEM_BYTES);
    cudaFuncSetAttribute(mma_gemm<TS5>, cudaFuncAttributeMaxDynamicSharedMemorySize, SMEM_BYTES);
    cudaFuncSetAttribute(mma_gemm<TS6>, cudaFuncAttributeMaxDynamicSharedMemorySize, SMEM_BYTES);
    cudaFuncSetAttribute(mma_gemm<TS8>, cudaFuncAttributeMaxDynamicSharedMemorySize, SMEM_BYTES);

    // h0 (fp32 + split), A_in split
    cudaMemcpyAsync(hf, prop, (size_t)Mrows * Dd * sizeof(float), cudaMemcpyDeviceToDevice);
    convRows_k<<<((long)Mrows * Dd + 255) / 256, 256>>>(prop, 256, hH, hL, Mrows, 256);
    convRows_k<<<((long)Mrows * EN + 255) / 256, 256>>>(A, 1024, AiH, AiL, Mrows, 512);

    // all 13 weight blocks -> transposed bf16 hi/lo, one fused launch
    {
        ConvJobs cj;
        int off = 0;
        auto add = [&](int idx, const float* src, bf16* hi, bf16* lo, int K, int N) {
            cj.j[idx] = {src, hi, lo, K, N, off};
            off += K * N;
        };
        add(0, W_in, WinTH, WinTL, 256, 256);
        add(1, W_in + 65536, WinTH + 65536, WinTL + 65536, 256, 256);
        add(2, W_in + 131072, WinTH + 131072, WinTL + 131072, 256, 256);
        add(3, W_in + 196608, WinTH + 196608, WinTL + 196608, 256, 256);
        add(4, W_r, WrzTH, WrzTL, 512, 256);
        add(5, W_z, WrzTH + 256 * 512, WrzTL + 256 * 512, 512, 256);
        add(6, W_t, WtTH, WtTL, 512, 256);
        add(7, W_mu1, WmvTH, WmvTL, 256, 256);
        add(8, W_var1, WmvTH + 256 * 256, WmvTL + 256 * 256, 256, 256);
        add(9, W_mu2, Wmu2TH, Wmu2TL, 256, 256);
        add(10, W_var2, Wvr2TH, Wvr2TL, 256, 256);
        add(11, W_d1, WdTH, WdTL, 256, 64);
        add(12, W_d2, WdTH + 64 * 256, WdTL + 64 * 256, 256, 512);
        cj.total = off;
        convAll_k<<<(cj.total + 255) / 256, 256>>>(cj);
    }

    for (int step = 0; step < STEPS; step++) {
        mma_gemm<TS1><<<dim3(16, 64, 1), 256, SMEM_BYTES>>>(
            TS1{hH, hL, WinTH, WinTL, b_in, iTH, iTL}, 256);
        mma_gemm<TS2><<<dim3(4, 1, 64), 256, SMEM_BYTES>>>(
            TS2{AiH, AiL, iTH, iTL, anH, anL}, 512);
        mma_gemm<TS3><<<dim3(8, 64, 1), 256, SMEM_BYTES>>>(
            TS3{anH, anL, hH, hL, WrzTH, WrzTL, b_r, b_z, hf, rhH, rhL, zb}, 512);
        mma_gemm<TS4><<<dim3(4, 64, 1), 256, SMEM_BYTES>>>(
            TS4{anH, anL, rhH, rhL, WtTH, WtTL, b_t, zb, hf, hH, hL}, 512);
    }

    mma_gemm<TS5><<<dim3(8, 64, 1), 256, SMEM_BYTES>>>(
        TS5{hH, hL, WmvTH, WmvTL, b_mu1, b_var1, t1H, t1L, t2H, t2L}, 256);
    mma_gemm<TS6><<<dim3(4, 64, 2), 256, SMEM_BYTES>>>(
        TS6{t1H, t1L, t2H, t2L, Wmu2TH, Wmu2TL, Wvr2TH, Wvr2TL,
            b_mu2, b_var2, out + OFF_MU, out + OFF_VAR}, 256);
    zlat_k<<<(Mrows * Dd + 255) / 256, 256>>>(out + OFF_MU, out + OFF_VAR, zlH, zlL);
    mma_gemm<TS8><<<dim3(9, 64, 1), 256, SMEM_BYTES>>>(
        TS8{zlH, zlL, WdTH, WdTL, b_d1, b_d2, out + OFF_NODE, out + OFF_EDGE}, 256);
}